// round 3
// baseline (speedup 1.0000x reference)
#include <cuda_runtime.h>
#include <math.h>

#define NP 768
#define DD 128
#define NH 8
#define AA 312

// ---------------- scratch (device globals, no allocation) ----------------
__device__ float g_ve[NP * NP];
__device__ float g_se[NP * NP];
__device__ float g_p [NP * DD];
__device__ float g_t [NP * DD];
__device__ float g_nrm[NP];
__device__ float g_ah[NP * NH];

// ---------------- row L2 norm (one warp per row) ----------------
__global__ void rownorm_k(const float* __restrict__ X, int cols, float* __restrict__ out) {
    int row = blockIdx.x;
    const float* x = X + (size_t)row * cols;
    float s = 0.f;
    for (int c = threadIdx.x; c < cols; c += 32) { float v = x[c]; s += v * v; }
    #pragma unroll
    for (int o = 16; o; o >>= 1) s += __shfl_down_sync(0xffffffffu, s, o);
    if (threadIdx.x == 0) out[row] = sqrtf(s);
}

// ---------------- cosine-sim "GEMM": C[i][j] = dot(Xi,Xj)/max(ni*nj,eps)*invtemp --------
__global__ void __launch_bounds__(256, 2)
sim_kernel(const float* __restrict__ X, int K,
           const float* __restrict__ nrm, float invtemp,
           float* __restrict__ C) {
    __shared__ float As[32][33];
    __shared__ float Bs[32][33];
    int i0 = blockIdx.y * 32, j0 = blockIdx.x * 32;
    int tx = threadIdx.x, ty = threadIdx.y;          // 16x16
    int t = ty * 16 + tx;
    float acc[2][2] = {{0.f,0.f},{0.f,0.f}};
    for (int k0 = 0; k0 < K; k0 += 32) {
        #pragma unroll
        for (int e = 0; e < 4; e++) {
            int idx = t + e * 256;
            int r = idx >> 5, c = idx & 31;
            int kk = k0 + c;
            float av = 0.f, bv = 0.f;
            if (kk < K) {
                av = X[(size_t)(i0 + r) * K + kk];
                bv = X[(size_t)(j0 + r) * K + kk];
            }
            As[r][c] = av;
            Bs[r][c] = bv;
        }
        __syncthreads();
        #pragma unroll
        for (int kk = 0; kk < 32; kk++) {
            float a0 = As[ty][kk],      a1 = As[ty + 16][kk];
            float b0 = Bs[tx][kk],      b1 = Bs[tx + 16][kk];
            acc[0][0] += a0 * b0; acc[0][1] += a0 * b1;
            acc[1][0] += a1 * b0; acc[1][1] += a1 * b1;
        }
        __syncthreads();
    }
    #pragma unroll
    for (int a = 0; a < 2; a++) {
        int i = i0 + ty + a * 16;
        float ni = nrm[i];
        #pragma unroll
        for (int b = 0; b < 2; b++) {
            int j = j0 + tx + b * 16;
            float den = fmaxf(ni * nrm[j], 1e-8f);
            C[(size_t)i * NP + j] = acc[a][b] / den * invtemp;
        }
    }
}

// ---------------- row softmax, in place, row length NP ----------------
__global__ void softmax_kernel(float* __restrict__ M) {
    __shared__ float buf[NP];
    __shared__ float red[8];
    int row = blockIdx.x;
    float* p = M + (size_t)row * NP;
    int t = threadIdx.x;                     // 256
    int wid = t >> 5, lane = t & 31;
    float mx = -1e30f;
    for (int c = t; c < NP; c += 256) { float v = p[c]; buf[c] = v; mx = fmaxf(mx, v); }
    #pragma unroll
    for (int o = 16; o; o >>= 1) mx = fmaxf(mx, __shfl_down_sync(0xffffffffu, mx, o));
    if (lane == 0) red[wid] = mx;
    __syncthreads();
    mx = red[0];
    #pragma unroll
    for (int w = 1; w < 8; w++) mx = fmaxf(mx, red[w]);
    float sum = 0.f;
    for (int c = t; c < NP; c += 256) { float e = expf(buf[c] - mx); buf[c] = e; sum += e; }
    __syncthreads();
    #pragma unroll
    for (int o = 16; o; o >>= 1) sum += __shfl_down_sync(0xffffffffu, sum, o);
    if (lane == 0) red[wid] = sum;
    __syncthreads();
    sum = 0.f;
    #pragma unroll
    for (int w = 0; w < 8; w++) sum += red[w];
    float inv = 1.f / sum;
    for (int c = t; c < NP; c += 256) p[c] = buf[c] * inv;
}

// ---------------- dual aggregation: p = edge@proto ; t = (edge+last)@proto ----------------
__global__ void __launch_bounds__(256, 2)
dualagg_kernel(const float* __restrict__ edge, const float* __restrict__ last,
               const float* __restrict__ proto,
               float* __restrict__ outp, float* __restrict__ outt) {
    __shared__ float E1[32][33];
    __shared__ float E2[32][33];
    __shared__ float Pr[32][33];
    int i0 = blockIdx.y * 32, d0 = blockIdx.x * 32;
    int tx = threadIdx.x, ty = threadIdx.y;
    int t = ty * 16 + tx;
    float ap[2][2] = {{0.f,0.f},{0.f,0.f}};
    float at[2][2] = {{0.f,0.f},{0.f,0.f}};
    for (int k0 = 0; k0 < NP; k0 += 32) {
        #pragma unroll
        for (int e = 0; e < 4; e++) {
            int idx = t + e * 256;
            int r = idx >> 5, c = idx & 31;
            E1[r][c] = edge[(size_t)(i0 + r) * NP + k0 + c];
            E2[r][c] = last[(size_t)(i0 + r) * NP + k0 + c];
            Pr[r][c] = proto[(size_t)(k0 + r) * DD + d0 + c];
        }
        __syncthreads();
        #pragma unroll
        for (int kk = 0; kk < 32; kk++) {
            float e10 = E1[ty][kk],      e11 = E1[ty + 16][kk];
            float s0  = e10 + E2[ty][kk], s1 = e11 + E2[ty + 16][kk];
            float p0  = Pr[kk][tx],      p1  = Pr[kk][tx + 16];
            ap[0][0] += e10 * p0; ap[0][1] += e10 * p1;
            ap[1][0] += e11 * p0; ap[1][1] += e11 * p1;
            at[0][0] += s0 * p0;  at[0][1] += s0 * p1;
            at[1][0] += s1 * p0;  at[1][1] += s1 * p1;
        }
        __syncthreads();
    }
    #pragma unroll
    for (int a = 0; a < 2; a++) {
        int i = i0 + ty + a * 16;
        #pragma unroll
        for (int b = 0; b < 2; b++) {
            int d = d0 + tx + b * 16;
            outp[(size_t)i * DD + d] = ap[a][b];
            outt[(size_t)i * DD + d] = at[a][b];
        }
    }
}

// ---------------- out = relu(LN(t@W^T + bias)*gamma + beta) + p  (one block per row) ------
__global__ void linear_ln_kernel(const float* __restrict__ T, const float* __restrict__ P,
                                 const float* __restrict__ W, const float* __restrict__ bias,
                                 const float* __restrict__ gamma, const float* __restrict__ beta,
                                 float* __restrict__ out) {
    __shared__ float trow[DD];
    __shared__ float red[4];
    int i = blockIdx.x, d = threadIdx.x;     // 128 threads
    int wid = d >> 5, lane = d & 31;
    trow[d] = T[(size_t)i * DD + d];
    __syncthreads();
    const float* w = W + (size_t)d * DD;
    float acc = bias[d];
    #pragma unroll 8
    for (int k = 0; k < DD; k++) acc += trow[k] * w[k];
    // mean
    float s = acc;
    #pragma unroll
    for (int o = 16; o; o >>= 1) s += __shfl_down_sync(0xffffffffu, s, o);
    if (lane == 0) red[wid] = s;
    __syncthreads();
    float m = (red[0] + red[1] + red[2] + red[3]) * (1.f / DD);
    __syncthreads();
    float dev = acc - m;
    float v = dev * dev;
    #pragma unroll
    for (int o = 16; o; o >>= 1) v += __shfl_down_sync(0xffffffffu, v, o);
    if (lane == 0) red[wid] = v;
    __syncthreads();
    float var = (red[0] + red[1] + red[2] + red[3]) * (1.f / DD);
    float y = dev * rsqrtf(var + 1e-5f) * gamma[d] + beta[d];
    out[(size_t)i * DD + d] = fmaxf(y, 0.f) + P[(size_t)i * DD + d];
}

// ---------------- A[i][h] = sum_d W1[h,d] * x[i,d]^2  (one warp per row) ----------------
__global__ void ah_kernel(const float* __restrict__ X, const float* __restrict__ W1,
                          float* __restrict__ A) {
    int i = blockIdx.x, lane = threadIdx.x;
    float acc[NH];
    #pragma unroll
    for (int h = 0; h < NH; h++) acc[h] = 0.f;
    for (int d = lane; d < DD; d += 32) {
        float x = X[(size_t)i * DD + d]; x *= x;
        #pragma unroll
        for (int h = 0; h < NH; h++) acc[h] += W1[h * DD + d] * x;
    }
    #pragma unroll
    for (int h = 0; h < NH; h++) {
        float s = acc[h];
        #pragma unroll
        for (int o = 16; o; o >>= 1) s += __shfl_down_sync(0xffffffffu, s, o);
        if (lane == 0) A[i * NH + h] = s;
    }
}

// ---------------- fused edge-MLP:  out[i,j] = tanh(MLP(instnorm)) * (last+eps)*invtemp ----
__global__ void __launch_bounds__(256, 2)
edge_kernel(const float* __restrict__ Pm, const float* __restrict__ A,
            const float* __restrict__ W1, const float* __restrict__ b1,
            const float* __restrict__ W2, const float* __restrict__ b2,
            const float* __restrict__ last, float invtemp,
            float* __restrict__ out) {
    __shared__ float Pi[32][33];
    __shared__ float Pj[32][33];
    __shared__ float Ws[NH][33];
    int i0 = blockIdx.y * 32, j0 = blockIdx.x * 32;
    int tx = threadIdx.x, ty = threadIdx.y;
    int t = ty * 16 + tx;
    float c[2][2][NH];
    #pragma unroll
    for (int a = 0; a < 2; a++)
        #pragma unroll
        for (int b = 0; b < 2; b++)
            #pragma unroll
            for (int h = 0; h < NH; h++) c[a][b][h] = 0.f;
    for (int k0 = 0; k0 < DD; k0 += 32) {
        #pragma unroll
        for (int e = 0; e < 4; e++) {
            int idx = t + e * 256;
            int r = idx >> 5, cc = idx & 31;
            Pi[r][cc] = Pm[(size_t)(i0 + r) * DD + k0 + cc];
            Pj[r][cc] = Pm[(size_t)(j0 + r) * DD + k0 + cc];
        }
        Ws[t >> 5][t & 31] = W1[(t >> 5) * DD + k0 + (t & 31)];  // 256 = NH*32
        __syncthreads();
        #pragma unroll
        for (int kk = 0; kk < 32; kk++) {
            float pi0 = Pi[ty][kk],      pi1 = Pi[ty + 16][kk];
            float pj0 = Pj[tx][kk],      pj1 = Pj[tx + 16][kk];
            float p00 = pi0 * pj0, p01 = pi0 * pj1;
            float p10 = pi1 * pj0, p11 = pi1 * pj1;
            #pragma unroll
            for (int h = 0; h < NH; h++) {
                float w = Ws[h][kk];
                c[0][0][h] += w * p00; c[0][1][h] += w * p01;
                c[1][0][h] += w * p10; c[1][1][h] += w * p11;
            }
        }
        __syncthreads();
    }
    float w2[NH], bb1[NH];
    #pragma unroll
    for (int h = 0; h < NH; h++) { w2[h] = W2[h]; bb1[h] = b1[h]; }
    float bb2 = b2[0];
    float Ai[2][NH], Aj[2][NH];
    #pragma unroll
    for (int h = 0; h < NH; h++) {
        Ai[0][h] = A[(i0 + ty) * NH + h];
        Ai[1][h] = A[(i0 + ty + 16) * NH + h];
        Aj[0][h] = A[(j0 + tx) * NH + h];
        Aj[1][h] = A[(j0 + tx + 16) * NH + h];
    }
    #pragma unroll
    for (int a = 0; a < 2; a++) {
        int i = i0 + ty + a * 16;
        #pragma unroll
        for (int b = 0; b < 2; b++) {
            int j = j0 + tx + b * 16;
            float hr[NH];
            float m = 0.f;
            #pragma unroll
            for (int h = 0; h < NH; h++) {
                hr[h] = Ai[a][h] + Aj[b][h] + bb1[h] - 2.f * c[a][b][h];
                m += hr[h];
            }
            m *= (1.f / NH);
            float v = 0.f;
            #pragma unroll
            for (int h = 0; h < NH; h++) { float dd = hr[h] - m; v += dd * dd; }
            v *= (1.f / NH);
            float inv = rsqrtf(v + 1e-5f);
            float acc = bb2;
            #pragma unroll
            for (int h = 0; h < NH; h++) {
                float hn = (hr[h] - m) * inv;
                hn = fmaxf(hn, 0.f);
                acc += hn * w2[h];
            }
            float e = tanhf(acc);
            out[(size_t)i * NP + j] = e * (last[(size_t)i * NP + j] + 1e-8f) * invtemp;
        }
    }
}

// =========================================================================================
extern "C" void kernel_launch(void* const* d_in, const int* in_sizes, int n_in,
                              void* d_out, int out_size) {
    const float* visual   = (const float*)d_in[0];
    const float* semantic = (const float*)d_in[1];
    const float* attrib   = (const float*)d_in[2];
    const float* Wvn  = (const float*)d_in[3];
    const float* bvn  = (const float*)d_in[4];
    const float* gvn  = (const float*)d_in[5];
    const float* betavn = (const float*)d_in[6];
    const float* Wve1 = (const float*)d_in[7];
    const float* bve1 = (const float*)d_in[8];
    const float* Wve2 = (const float*)d_in[9];
    const float* bve2 = (const float*)d_in[10];
    const float* Wsn  = (const float*)d_in[11];
    const float* bsn  = (const float*)d_in[12];
    const float* gsn  = (const float*)d_in[13];
    const float* betasn = (const float*)d_in[14];
    const float* Wse1 = (const float*)d_in[15];
    const float* bse1 = (const float*)d_in[16];
    const float* Wse2 = (const float*)d_in[17];
    const float* bse2 = (const float*)d_in[18];

    float* out = (float*)d_out;
    float* vp  = out;
    float* sp  = out + NP * DD;
    float* ve2 = out + 2 * NP * DD;
    float* se2 = ve2 + NP * NP;

    float *ve, *se, *gp, *gt, *gn, *ga;
    cudaGetSymbolAddress((void**)&ve, g_ve);
    cudaGetSymbolAddress((void**)&se, g_se);
    cudaGetSymbolAddress((void**)&gp, g_p);
    cudaGetSymbolAddress((void**)&gt, g_t);
    cudaGetSymbolAddress((void**)&gn, g_nrm);
    cudaGetSymbolAddress((void**)&ga, g_ah);

    dim3 b16(16, 16);
    dim3 gNN(NP / 32, NP / 32);   // 24x24
    dim3 gND(DD / 32, NP / 32);   // 4x24

    // ve = softmax(cos_sim(visual)/0.1)
    rownorm_k<<<NP, 32>>>(visual, DD, gn);
    sim_kernel<<<gNN, b16>>>(visual, DD, gn, 10.f, ve);
    softmax_kernel<<<NP, 256>>>(ve);

    // se = softmax(cos_sim(attribute)/0.1)
    rownorm_k<<<NP, 32>>>(attrib, AA, gn);
    sim_kernel<<<gNN, b16>>>(attrib, AA, gn, 10.f, se);
    softmax_kernel<<<NP, 256>>>(se);

    // vp = node_update(visual, last=se, edge=ve)
    dualagg_kernel<<<gND, b16>>>(ve, se, visual, gp, gt);
    linear_ln_kernel<<<NP, DD>>>(gt, gp, Wvn, bvn, gvn, betavn, vp);

    // ve2 = edge_update(vp, last=ve, temp=10)
    ah_kernel<<<NP, 32>>>(vp, Wve1, ga);
    edge_kernel<<<gNN, b16>>>(vp, ga, Wve1, bve1, Wve2, bve2, ve, 0.1f, ve2);
    softmax_kernel<<<NP, 256>>>(ve2);

    // sp = node_update(semantic, last=ve2, edge=se)
    dualagg_kernel<<<gND, b16>>>(se, ve2, semantic, gp, gt);
    linear_ln_kernel<<<NP, DD>>>(gt, gp, Wsn, bsn, gsn, betasn, sp);

    // se2 = edge_update(sp, last=se, temp=10)
    ah_kernel<<<NP, 32>>>(sp, Wse1, ga);
    edge_kernel<<<gNN, b16>>>(sp, ga, Wse1, bse1, Wse2, bse2, se, 0.1f, se2);
    softmax_kernel<<<NP, 256>>>(se2);
}